// round 1
// baseline (speedup 1.0000x reference)
#include <cuda_runtime.h>
#include <math_constants.h>

// ScalarDistanceDeepSet: pooled_b = sum_{i<j<L_b} g(dm[b,i,j]); g is a 1->64->128
// relu MLP == piecewise-linear in s with 65 segments. We precompute per-segment
// exact (A, C) tables so each pair costs one segment lookup + 128 FMAs.

#define NB    32
#define NN    256
#define P1    64     // PHI1
#define P2    128    // PHI2
#define R1    256    // RHO1
#define R2    128    // RHO2
#define OD    64     // OUT
#define NSEG  65
#define NBLK  16     // pair-kernel blocks per batch
#define TILE  128

__device__ float g_tsorted[P1];
__device__ int   g_rank[P1];
__device__ float g_A[NSEG * P2];
__device__ float g_C[NSEG * P2];
__device__ float g_partial[NB * NBLK * P2];

// ---------------------------------------------------------------------------
// Setup 1: breakpoints t_k = -b1_k / w1_k, rank of each breakpoint (stable),
// and the sorted breakpoint array used for the per-pair binary search.
// ---------------------------------------------------------------------------
__global__ void setup_breaks(const float* __restrict__ W1,
                             const float* __restrict__ b1) {
    __shared__ float t[P1];
    int k = threadIdx.x;  // 0..63
    float w = W1[k], b = b1[k];
    float tk = (w != 0.0f) ? (-b / w) : CUDART_INF_F;
    t[k] = tk;
    __syncthreads();
    int r = 0;
    for (int kk = 0; kk < P1; kk++) {
        float tv = t[kk];
        if (tv < tk || (tv == tk && kk < k)) r++;
    }
    g_rank[k] = r;
    g_tsorted[r] = tk;
}

// ---------------------------------------------------------------------------
// Setup 2: exact per-segment linear tables.
// Segment m (0..64) covers s in (t_sorted[m-1], t_sorted[m]).
// Unit k is active in segment m iff:
//   w>0 : s > t_k  <=> m > rank_k
//   w<0 : s < t_k  <=> m <= rank_k
//   w=0 : b > 0    (always/never)
// A[m][f] = sum_active w_k * W2[k][f];  C[m][f] = b2[f] + sum_active b_k * W2[k][f]
// ---------------------------------------------------------------------------
__global__ void setup_tables(const float* __restrict__ W1,
                             const float* __restrict__ b1,
                             const float* __restrict__ W2,
                             const float* __restrict__ b2) {
    int m = blockIdx.x;    // segment
    int f = threadIdx.x;   // output feature 0..127
    float a = 0.0f, c = b2[f];
    for (int k = 0; k < P1; k++) {
        float w = W1[k], b = b1[k];
        int r = g_rank[k];
        bool active = (w > 0.0f) ? (m > r)
                    : (w < 0.0f) ? (m <= r)
                    : (b > 0.0f);
        if (active) {
            float w2 = W2[k * P2 + f];
            a = fmaf(w, w2, a);
            c = fmaf(b, w2, c);
        }
    }
    g_A[m * P2 + f] = a;
    g_C[m * P2 + f] = c;
}

// ---------------------------------------------------------------------------
// Main pair kernel: grid (NBLK, NB), 128 threads. Thread f owns feature f.
// Block (kblk, b) handles rows i = kblk, kblk+NBLK, ... of batch b.
// Phase 1 (per tile of up to 128 j's): coalesced load of dm row segment,
// binary search for segment id. Phase 2: each thread accumulates
// relu(A[seg]*s + C[seg]) for its feature across the tile.
// ---------------------------------------------------------------------------
__global__ void __launch_bounds__(128)
pair_kernel(const float* __restrict__ dm, const int* __restrict__ lengths) {
    extern __shared__ float smem[];
    float2* shAC = (float2*)smem;                    // NSEG*P2 float2 (A,C)
    float*  sht  = smem + NSEG * P2 * 2;             // 64 sorted breakpoints
    float*  shs  = sht + P1;                         // TILE scalars
    int*    shm  = (int*)(shs + TILE);               // TILE segment offsets

    int f    = threadIdx.x;
    int kblk = blockIdx.x;
    int b    = blockIdx.y;

    // Stage tables into shared (interleaved A,C for one LDS.64 per lookup)
    for (int i = f; i < NSEG * P2; i += 128)
        shAC[i] = make_float2(g_A[i], g_C[i]);
    if (f < P1) sht[f] = g_tsorted[f];
    __syncthreads();

    int L = lengths[b];
    float acc = 0.0f;
    const float* dmb = dm + (size_t)b * NN * NN;

    for (int i = kblk; i < L - 1; i += NBLK) {
        const float* row = dmb + i * NN;
        for (int j0 = i + 1; j0 < L; j0 += TILE) {
            int cnt = min(TILE, L - j0);
            if (f < cnt) {
                float s = row[j0 + f];
                int lo = 0, hi = P1;
                while (lo < hi) {               // count of t_sorted < s
                    int mid = (lo + hi) >> 1;
                    if (sht[mid] < s) lo = mid + 1; else hi = mid;
                }
                shs[f] = s;
                shm[f] = lo * P2;
            }
            __syncthreads();
            #pragma unroll 4
            for (int t = 0; t < cnt; t++) {
                float  s  = shs[t];
                float2 ac = shAC[shm[t] + f];
                acc += fmaxf(0.0f, fmaf(ac.x, s, ac.y));
            }
            __syncthreads();
        }
    }
    g_partial[(b * NBLK + kblk) * P2 + f] = acc;
}

// ---------------------------------------------------------------------------
// Head: reduce NBLK partials -> pooled, then 128->256->128->64 MLP.
// One block per batch, 256 threads.
// ---------------------------------------------------------------------------
__global__ void __launch_bounds__(256)
mlp_kernel(const float* __restrict__ W3, const float* __restrict__ b3,
           const float* __restrict__ W4, const float* __restrict__ b4,
           const float* __restrict__ W5, const float* __restrict__ b5,
           float* __restrict__ out) {
    __shared__ float pooled[P2];
    __shared__ float r1[R1];
    __shared__ float r2[R2];
    int b = blockIdx.x, t = threadIdx.x;

    if (t < P2) {
        float v = 0.0f;
        for (int k = 0; k < NBLK; k++)
            v += g_partial[(b * NBLK + k) * P2 + t];
        pooled[t] = v;
    }
    __syncthreads();

    {   // r1 = relu(pooled @ W3 + b3), W3 [P2][R1]
        float v = b3[t];
        #pragma unroll 8
        for (int k = 0; k < P2; k++)
            v = fmaf(pooled[k], W3[k * R1 + t], v);
        r1[t] = fmaxf(v, 0.0f);
    }
    __syncthreads();

    if (t < R2) {   // r2 = relu(r1 @ W4 + b4), W4 [R1][R2]
        float v = b4[t];
        #pragma unroll 8
        for (int k = 0; k < R1; k++)
            v = fmaf(r1[k], W4[k * R2 + t], v);
        r2[t] = fmaxf(v, 0.0f);
    }
    __syncthreads();

    if (t < OD) {   // out = r2 @ W5 + b5, W5 [R2][OD]
        float v = b5[t];
        #pragma unroll 8
        for (int k = 0; k < R2; k++)
            v = fmaf(r2[k], W5[k * OD + t], v);
        out[b * OD + t] = v;
    }
}

// ---------------------------------------------------------------------------
extern "C" void kernel_launch(void* const* d_in, const int* in_sizes, int n_in,
                              void* d_out, int out_size) {
    const float* dm      = (const float*)d_in[0];
    const int*   lengths = (const int*)  d_in[1];
    const float* W1 = (const float*)d_in[2],  *b1 = (const float*)d_in[3];
    const float* W2 = (const float*)d_in[4],  *b2 = (const float*)d_in[5];
    const float* W3 = (const float*)d_in[6],  *b3 = (const float*)d_in[7];
    const float* W4 = (const float*)d_in[8],  *b4 = (const float*)d_in[9];
    const float* W5 = (const float*)d_in[10], *b5 = (const float*)d_in[11];
    float* out = (float*)d_out;

    const int smem_bytes = NSEG * P2 * 2 * (int)sizeof(float)   // A,C interleaved
                         + P1 * (int)sizeof(float)              // t_sorted
                         + TILE * (int)sizeof(float)            // scalars
                         + TILE * (int)sizeof(int);             // segment offsets
    cudaFuncSetAttribute((const void*)pair_kernel,
                         cudaFuncAttributeMaxDynamicSharedMemorySize, smem_bytes);

    setup_breaks<<<1, P1>>>(W1, b1);
    setup_tables<<<NSEG, P2>>>(W1, b1, W2, b2);
    pair_kernel<<<dim3(NBLK, NB), 128, smem_bytes>>>(dm, lengths);
    mlp_kernel<<<NB, 256>>>(W3, b3, W4, b4, W5, b5, out);
}

// round 2
// speedup vs baseline: 1.2106x; 1.2106x over previous
#include <cuda_runtime.h>
#include <math_constants.h>

// ScalarDistanceDeepSet via exact piecewise-linear collapse + cell histogram.
// g(s) (1->64->128 relu MLP) is piecewise-linear: 64 layer-1 breakpoints give 65
// segments with per-(segment,feature) (a,c); each feature's relu crossing
// theta=-c/a adds batch-independent boundaries -> 65*129=8385 cells on which all
// features are linear. Per pair: binary search -> (count, sum_s) histogram with
// integer atomics (deterministic). Pooled = prefix-sum algebra. Head MLP fused.

#define NB    32
#define NN    256
#define P1    64
#define P2    128
#define R1    256
#define R2    128
#define OD    64
#define NSEG  65
#define NCELL 129                 // cells per segment
#define NSLOT (NSEG * NCELL)      // 8385
#define SPLIT 16                  // hist blocks per batch
#define SCALE_F   67108864.0f     // 2^26
#define INV_SCALE (1.0 / 67108864.0)

__device__ float     g_tsorted[P1];
__device__ int       g_rank[P1];
__device__ float     g_A[NSEG * P2];
__device__ float     g_C[NSEG * P2];
__device__ float     g_thsort[NSEG * P2];
__device__ int2      g_range[NSEG * P2];          // [rlo, rhi) active cell range
__device__ long long g_hs[NB * NSLOT];            // fixed-point sum(s) per cell
__device__ int       g_hc[NB * NSLOT];            // count per cell

// ---------------------------------------------------------------------------
__global__ void zero_hist() {
    int n = NB * NSLOT;
    for (int i = blockIdx.x * blockDim.x + threadIdx.x; i < n;
         i += gridDim.x * blockDim.x) {
        g_hs[i] = 0;
        g_hc[i] = 0;
    }
}

// ---------------------------------------------------------------------------
__global__ void setup_breaks(const float* __restrict__ W1,
                             const float* __restrict__ b1) {
    __shared__ float t[P1];
    int k = threadIdx.x;
    float w = W1[k], b = b1[k];
    float tk = (w != 0.0f) ? (-b / w) : CUDART_INF_F;
    t[k] = tk;
    __syncthreads();
    int r = 0;
    for (int kk = 0; kk < P1; kk++) {
        float tv = t[kk];
        if (tv < tk || (tv == tk && kk < k)) r++;
    }
    g_rank[k] = r;
    g_tsorted[r] = tk;
}

// ---------------------------------------------------------------------------
// Per (segment m, feature f): exact (a, c); relu crossing theta clamped into
// the segment; rank p of theta among the segment's 128 thetas; active cell
// range [rlo, rhi). Cells: r(s) = #{theta_sorted < s}.
// ---------------------------------------------------------------------------
__global__ void setup_tables(const float* __restrict__ W1,
                             const float* __restrict__ b1,
                             const float* __restrict__ W2,
                             const float* __restrict__ b2) {
    __shared__ float sth[P2];
    int m = blockIdx.x;
    int f = threadIdx.x;
    float a = 0.0f, c = b2[f];
    for (int k = 0; k < P1; k++) {
        float w = W1[k], b = b1[k];
        int r = g_rank[k];
        bool active = (w > 0.0f) ? (m > r)
                    : (w < 0.0f) ? (m <= r)
                    : (b > 0.0f);
        if (active) {
            float w2 = W2[k * P2 + f];
            a = fmaf(w, w2, a);
            c = fmaf(b, w2, c);
        }
    }
    int idx = m * P2 + f;
    g_A[idx] = a;
    g_C[idx] = c;

    float lo_t = (m == 0)        ? -CUDART_INF_F : g_tsorted[m - 1];
    float hi_t = (m == NSEG - 1) ?  CUDART_INF_F : g_tsorted[m];
    float th;
    if (a != 0.0f) {
        th = -c / a;
        th = fminf(fmaxf(th, lo_t), hi_t);
    } else {
        th = lo_t;
    }
    sth[f] = th;
    __syncthreads();
    int p = 0;
    for (int k = 0; k < P2; k++) {
        float tv = sth[k];
        if (tv < th || (tv == th && k < f)) p++;
    }
    g_thsort[m * P2 + p] = th;

    int rlo, rhi;
    if (a > 0.0f)      { rlo = p + 1; rhi = NCELL; }
    else if (a < 0.0f) { rlo = 0;     rhi = p + 1; }
    else               { rlo = 0;     rhi = (c > 0.0f) ? NCELL : 0; }
    g_range[idx] = make_int2(rlo, rhi);
}

// ---------------------------------------------------------------------------
// Histogram: grid (SPLIT, NB), 256 threads. Per valid pair s=dm[b,i,j] (i<j<L):
// segment search (6 steps) + intra-segment theta search (7 steps) + 2 atomics.
// ---------------------------------------------------------------------------
__global__ void __launch_bounds__(256)
hist_kernel(const float* __restrict__ dm, const int* __restrict__ lengths) {
    __shared__ float st[P1];
    __shared__ float sth[NSEG * P2];   // 33.3 KB

    int tid = threadIdx.x;
    int b   = blockIdx.y;
    if (tid < P1) st[tid] = g_tsorted[tid];
    for (int i = tid; i < NSEG * P2; i += 256) sth[i] = g_thsort[i];
    __syncthreads();

    int L = lengths[b];
    const float* dmb = dm + (size_t)b * NN * NN;
    unsigned long long* hs = (unsigned long long*)(g_hs + (size_t)b * NSLOT);
    int* hc = g_hc + (size_t)b * NSLOT;

    for (int i = blockIdx.x; i < L - 1; i += SPLIT) {
        const float* row = dmb + i * NN;
        for (int j = i + 1 + tid; j < L; j += 256) {
            float s = row[j];
            int lo = 0, hi = P1;                 // segment = #{t < s}
            while (lo < hi) {
                int mid = (lo + hi) >> 1;
                if (st[mid] < s) lo = mid + 1; else hi = mid;
            }
            int m = lo;
            const float* th = sth + (m << 7);
            int l2 = 0, h2 = P2;                 // cell = #{theta < s}
            while (l2 < h2) {
                int mid = (l2 + h2) >> 1;
                if (th[mid] < s) l2 = mid + 1; else h2 = mid;
            }
            int slot = m * NCELL + l2;
            long long q = llrintf(s * SCALE_F);
            atomicAdd(&hs[slot], (unsigned long long)q);
            atomicAdd(&hc[slot], 1);
        }
    }
}

// ---------------------------------------------------------------------------
// Per batch: exclusive prefix over 8385 cells (int64 + int32), evaluate pooled
// via per-(m,f) range algebra, then fused 128->256->128->64 head with K-split.
// One block per batch, 1024 threads, ~115 KB dynamic smem.
// ---------------------------------------------------------------------------
#define CH 9   // 1024*9 >= 8385

__global__ void __launch_bounds__(1024)
evalhead_kernel(const float* __restrict__ W3, const float* __restrict__ b3,
                const float* __restrict__ W4, const float* __restrict__ b4,
                const float* __restrict__ W5, const float* __restrict__ b5,
                float* __restrict__ out) {
    extern __shared__ char dyn[];
    long long* ps   = (long long*)dyn;          // NSLOT+1
    long long* auxS = ps + (NSLOT + 1);         // 1024
    int*       pc   = (int*)(auxS + 1024);      // NSLOT+1
    int*       auxC = pc + (NSLOT + 1);         // 1024
    float*     part = (float*)auxS;             // reused after scan (1024)
    float*     pooled = (float*)(auxC + 1024);  // 128
    float*     r1     = pooled + P2;            // 256
    float*     r2     = r1 + R1;                // 128

    int b = blockIdx.x, t = threadIdx.x;
    const long long* hs = g_hs + (size_t)b * NSLOT;
    const int*       hc = g_hc + (size_t)b * NSLOT;

    // chunk-local exclusive prefixes
    int s0 = t * CH;
    long long runS = 0; int runC = 0;
    #pragma unroll
    for (int e = 0; e < CH; e++) {
        int idx = s0 + e;
        if (idx < NSLOT) {
            ps[idx] = runS; pc[idx] = runC;
            runS += hs[idx]; runC += hc[idx];
        }
    }
    auxS[t] = runS; auxC[t] = runC;
    __syncthreads();
    // inclusive scan of chunk totals
    for (int off = 1; off < 1024; off <<= 1) {
        long long vs = auxS[t]; int vc = auxC[t];
        if (t >= off) { vs += auxS[t - off]; vc += auxC[t - off]; }
        __syncthreads();
        auxS[t] = vs; auxC[t] = vc;
        __syncthreads();
    }
    long long offS = (t == 0) ? 0 : auxS[t - 1];
    int       offC = (t == 0) ? 0 : auxC[t - 1];
    #pragma unroll
    for (int e = 0; e < CH; e++) {
        int idx = s0 + e;
        if (idx < NSLOT) { ps[idx] += offS; pc[idx] += offC; }
    }
    if (t == 1023) { ps[NSLOT] = auxS[1023]; pc[NSLOT] = auxC[1023]; }
    __syncthreads();

    // pooled[f] = sum_m a*(sum s in range) + c*(count in range)
    if (t < P2) {
        float acc = 0.0f;
        #pragma unroll 4
        for (int m = 0; m < NSEG; m++) {
            int idx = m * P2 + t;
            float a = g_A[idx], c = g_C[idx];
            int2 rg = g_range[idx];
            int base = m * NCELL;
            long long ds = ps[base + rg.y] - ps[base + rg.x];
            int       dc = pc[base + rg.y] - pc[base + rg.x];
            acc += a * (float)((double)ds * INV_SCALE) + c * (float)dc;
        }
        pooled[t] = acc;
    }
    __syncthreads();

    // layer1: 256 outputs, 4-way K split (K=128)
    {
        int o = t & 255, ch = t >> 8;
        float v = 0.0f;
        int k0 = ch * 32;
        #pragma unroll
        for (int k = 0; k < 32; k++)
            v = fmaf(pooled[k0 + k], W3[(k0 + k) * R1 + o], v);
        part[t] = v;
    }
    __syncthreads();
    if (t < R1)
        r1[t] = fmaxf(b3[t] + part[t] + part[t + 256] + part[t + 512] + part[t + 768], 0.0f);
    __syncthreads();

    // layer2: 128 outputs, 8-way K split (K=256)
    {
        int o = t & 127, ch = t >> 7;
        float v = 0.0f;
        int k0 = ch * 32;
        #pragma unroll
        for (int k = 0; k < 32; k++)
            v = fmaf(r1[k0 + k], W4[(k0 + k) * R2 + o], v);
        part[t] = v;
    }
    __syncthreads();
    if (t < R2) {
        float v = b4[t];
        #pragma unroll
        for (int j = 0; j < 8; j++) v += part[t + 128 * j];
        r2[t] = fmaxf(v, 0.0f);
    }
    __syncthreads();

    // layer3: 64 outputs, 16-way K split (K=128)
    {
        int o = t & 63, ch = t >> 6;
        float v = 0.0f;
        int k0 = ch * 8;
        #pragma unroll
        for (int k = 0; k < 8; k++)
            v = fmaf(r2[k0 + k], W5[(k0 + k) * OD + o], v);
        part[t] = v;
    }
    __syncthreads();
    if (t < OD) {
        float v = b5[t];
        #pragma unroll
        for (int j = 0; j < 16; j++) v += part[t + 64 * j];
        out[b * OD + t] = v;
    }
}

// ---------------------------------------------------------------------------
extern "C" void kernel_launch(void* const* d_in, const int* in_sizes, int n_in,
                              void* d_out, int out_size) {
    const float* dm      = (const float*)d_in[0];
    const int*   lengths = (const int*)  d_in[1];
    const float* W1 = (const float*)d_in[2],  *b1 = (const float*)d_in[3];
    const float* W2 = (const float*)d_in[4],  *b2 = (const float*)d_in[5];
    const float* W3 = (const float*)d_in[6],  *b3 = (const float*)d_in[7];
    const float* W4 = (const float*)d_in[8],  *b4 = (const float*)d_in[9];
    const float* W5 = (const float*)d_in[10], *b5 = (const float*)d_in[11];
    float* out = (float*)d_out;

    const int smem_eval = (NSLOT + 1 + 1024) * 8 + (NSLOT + 1 + 1024) * 4
                        + (P2 + R1 + R2) * 4;
    cudaFuncSetAttribute((const void*)evalhead_kernel,
                         cudaFuncAttributeMaxDynamicSharedMemorySize, smem_eval);

    zero_hist<<<512, 512>>>();
    setup_breaks<<<1, P1>>>(W1, b1);
    setup_tables<<<NSEG, P2>>>(W1, b1, W2, b2);
    hist_kernel<<<dim3(SPLIT, NB), 256>>>(dm, lengths);
    evalhead_kernel<<<NB, 1024, smem_eval>>>(W3, b3, W4, b4, W5, b5, out);
}

// round 3
// speedup vs baseline: 1.5856x; 1.3097x over previous
#include <cuda_runtime.h>
#include <math_constants.h>

// ScalarDistanceDeepSet via exact piecewise-linear collapse + cell histogram.
// g(s) (1->64->128 relu MLP) is piecewise-linear: 64 layer-1 breakpoints -> 65
// segments with per-(segment,feature) (a,c); per-feature relu crossings theta
// (clamped into their segment) give 8384 global sorted boundaries -> 8385 cells
// on which every feature is linear. Per pair: one branchless 14-step search
// (ILP-4 across rows) + 2 integer atomics (deterministic). Pooled recovered by
// 65 independent per-segment warp scans + range algebra. Head MLP fused.

#define NB    32
#define NN    256
#define P1    64
#define P2    128
#define R1    256
#define R2    128
#define OD    64
#define NSEG  65
#define NCELL 129
#define NSLOT (NSEG * NCELL)      // 8385 cells
#define NBND  (NSLOT - 1)         // 8384 boundaries
#define SCALE_F   67108864.0f     // 2^26
#define INV_SCALE (1.0 / 67108864.0)
#define HIST_GRID 592

__device__ float     g_tsorted[P1];
__device__ int       g_rank[P1];
__device__ float     g_A[NSEG * P2];
__device__ float     g_C[NSEG * P2];
__device__ float     g_bnd[NBND];                 // flat sorted boundaries
__device__ int2      g_range[NSEG * P2];          // [rlo, rhi) active cell range
__device__ long long g_hs[NB * NSLOT];            // fixed-point sum(s) per cell
__device__ int       g_hc[NB * NSLOT];            // count per cell

// ---------------------------------------------------------------------------
// Setup 0: block 0 computes breakpoints + ranks; other blocks zero histograms.
// ---------------------------------------------------------------------------
__global__ void setup0(const float* __restrict__ W1,
                       const float* __restrict__ b1) {
    if (blockIdx.x == 0) {
        __shared__ float t[P1];
        int k = threadIdx.x;
        float tk = 0.0f;
        if (k < P1) {
            float w = W1[k], b = b1[k];
            tk = (w != 0.0f) ? (-b / w) : CUDART_INF_F;
            t[k] = tk;
        }
        __syncthreads();
        if (k < P1) {
            int r = 0;
            for (int kk = 0; kk < P1; kk++) {
                float tv = t[kk];
                if (tv < tk || (tv == tk && kk < k)) r++;
            }
            g_rank[k] = r;
            g_tsorted[r] = tk;
        }
    } else {
        int idx = (blockIdx.x - 1) * blockDim.x + threadIdx.x;
        int stride = (gridDim.x - 1) * blockDim.x;
        for (int i = idx; i < NB * NSLOT; i += stride) {
            g_hs[i] = 0;
            g_hc[i] = 0;
        }
    }
}

// ---------------------------------------------------------------------------
// Setup 1: exact per-(segment m, feature f) (a,c), clamped relu crossing theta,
// its rank p within the segment, active cell range, and the flat boundary
// array: g_bnd[m*129 + p] = theta, g_bnd[m*129 + 128] = t_sorted[m].
// ---------------------------------------------------------------------------
__global__ void setup_tables(const float* __restrict__ W1,
                             const float* __restrict__ b1,
                             const float* __restrict__ W2,
                             const float* __restrict__ b2) {
    __shared__ float sth[P2];
    int m = blockIdx.x;
    int f = threadIdx.x;
    float a = 0.0f, c = b2[f];
    for (int k = 0; k < P1; k++) {
        float w = W1[k], b = b1[k];
        int r = g_rank[k];
        bool active = (w > 0.0f) ? (m > r)
                    : (w < 0.0f) ? (m <= r)
                    : (b > 0.0f);
        if (active) {
            float w2 = W2[k * P2 + f];
            a = fmaf(w, w2, a);
            c = fmaf(b, w2, c);
        }
    }
    int idx = m * P2 + f;
    g_A[idx] = a;
    g_C[idx] = c;

    float lo_t = (m == 0)        ? -CUDART_INF_F : g_tsorted[m - 1];
    float hi_t = (m == NSEG - 1) ?  CUDART_INF_F : g_tsorted[m];
    float th;
    if (a != 0.0f) {
        th = -c / a;
        th = fminf(fmaxf(th, lo_t), hi_t);
    } else {
        th = lo_t;
    }
    sth[f] = th;
    __syncthreads();
    int p = 0;
    for (int k = 0; k < P2; k++) {
        float tv = sth[k];
        if (tv < th || (tv == th && k < f)) p++;
    }
    g_bnd[m * NCELL + p] = th;
    if (f == 0 && m < NSEG - 1) g_bnd[m * NCELL + P2] = g_tsorted[m];

    int rlo, rhi;
    if (a > 0.0f)      { rlo = p + 1; rhi = NCELL; }
    else if (a < 0.0f) { rlo = 0;     rhi = p + 1; }
    else               { rlo = 0;     rhi = (c > 0.0f) ? NCELL : 0; }
    g_range[idx] = make_int2(rlo, rhi);
}

// ---------------------------------------------------------------------------
// Histogram. 1-D grid; task = 4 consecutive rows of one batch. Thread tid owns
// column j=tid across the 4 rows -> 4 independent branchless searches per
// thread (ILP-4 hides the dependent-LDS chain). 2 atomics per valid pair.
// ---------------------------------------------------------------------------
__global__ void __launch_bounds__(256)
hist_kernel(const float* __restrict__ dm, const int* __restrict__ lengths) {
    __shared__ float sb[NBND];     // 33.5 KB
    int tid = threadIdx.x;
    for (int i = tid; i < NBND; i += 256) sb[i] = g_bnd[i];
    __syncthreads();

    const int ntask = NB * (NN / 4);   // 2048
    for (int task = blockIdx.x; task < ntask; task += gridDim.x) {
        int b  = task & 31;
        int i0 = (task >> 5) << 2;
        int L  = __ldg(lengths + b);
        if (i0 >= L - 1) continue;

        const float* rowp = dm + ((size_t)b << 16) + ((size_t)i0 << 8) + tid;
        float s[4]; int n[4], pos[4];
        #pragma unroll
        for (int r = 0; r < 4; r++) {
            int i = i0 + r;
            bool valid = (i < L - 1) && (tid > i) && (tid < L);
            s[r]   = valid ? rowp[r << 8] : 0.0f;
            pos[r] = 0;
            n[r]   = valid ? NBND : 0;
        }
        #pragma unroll
        for (int it = 0; it < 14; it++) {
            #pragma unroll
            for (int r = 0; r < 4; r++) {
                if (n[r] > 0) {
                    int half = n[r] >> 1;
                    int mid  = pos[r] + half;
                    if (sb[mid] < s[r]) { pos[r] = mid + 1; n[r] -= half + 1; }
                    else                { n[r] = half; }
                }
            }
        }
        unsigned long long* hsb = (unsigned long long*)g_hs + (size_t)b * NSLOT;
        int* hcb = g_hc + (size_t)b * NSLOT;
        #pragma unroll
        for (int r = 0; r < 4; r++) {
            int i = i0 + r;
            bool valid = (i < L - 1) && (tid > i) && (tid < L);
            if (valid) {
                long long q = llrintf(s[r] * SCALE_F);
                atomicAdd(&hsb[pos[r]], (unsigned long long)q);
                atomicAdd(&hcb[pos[r]], 1);
            }
        }
    }
}

// ---------------------------------------------------------------------------
// Per batch (1 block, 1024 threads): 65 independent per-segment warp scans
// (range algebra never crosses segments), pooled via 8-way m-split, then the
// fused 128->256->128->64 head with K-split.
// ---------------------------------------------------------------------------
__global__ void __launch_bounds__(1024)
evalhead_kernel(const float* __restrict__ W3, const float* __restrict__ b3,
                const float* __restrict__ W4, const float* __restrict__ b4,
                const float* __restrict__ W5, const float* __restrict__ b5,
                float* __restrict__ out) {
    extern __shared__ char dyn[];
    long long* ps     = (long long*)dyn;           // NSEG*130 = 8450
    int*       pc     = (int*)(ps + NSEG * 130);   // 8450
    float*     part   = (float*)(pc + NSEG * 130); // 1024
    float*     pooled = part + 1024;               // 128
    float*     r1     = pooled + P2;               // 256
    float*     r2     = r1 + R1;                   // 128

    int b = blockIdx.x, t = threadIdx.x;
    int warp = t >> 5, lane = t & 31;
    const long long* hs = g_hs + (size_t)b * NSLOT;
    const int*       hc = g_hc + (size_t)b * NSLOT;

    // per-segment exclusive scans: ps[m*130 + r] = sum cells [m*129, m*129+r)
    for (int m = warp; m < NSEG; m += 32) {
        int cbase = m * NCELL;
        int base  = lane * 4;
        int ncl   = (lane == 31) ? 5 : 4;
        long long ls[5]; int lc[5];
        long long runS = 0; int runC = 0;
        #pragma unroll
        for (int e = 0; e < 5; e++) {
            if (e < ncl) {
                ls[e] = runS; lc[e] = runC;
                runS += hs[cbase + base + e];
                runC += hc[cbase + base + e];
            }
        }
        long long incS = runS; int incC = runC;
        #pragma unroll
        for (int off = 1; off < 32; off <<= 1) {
            long long vS = __shfl_up_sync(0xffffffffu, incS, off);
            int       vC = __shfl_up_sync(0xffffffffu, incC, off);
            if (lane >= off) { incS += vS; incC += vC; }
        }
        long long exS = incS - runS; int exC = incC - runC;
        int sbase = m * 130;
        #pragma unroll
        for (int e = 0; e < 5; e++) {
            if (e < ncl) {
                ps[sbase + base + e] = exS + ls[e];
                pc[sbase + base + e] = exC + lc[e];
            }
        }
        if (lane == 31) { ps[sbase + NCELL] = incS; pc[sbase + NCELL] = incC; }
    }
    __syncthreads();

    // pooled[f] = sum_m a*(sum s over range) + c*(count over range)
    {
        int f = t & 127, g = t >> 7;   // 8 m-groups
        float acc = 0.0f;
        for (int m = g; m < NSEG; m += 8) {
            int idx = m * P2 + f;
            float a = g_A[idx], c = g_C[idx];
            int2 rg = g_range[idx];
            int sbase = m * 130;
            long long ds = ps[sbase + rg.y] - ps[sbase + rg.x];
            int       dc = pc[sbase + rg.y] - pc[sbase + rg.x];
            acc += a * (float)((double)ds * INV_SCALE) + c * (float)dc;
        }
        part[t] = acc;
    }
    __syncthreads();
    if (t < P2) {
        float v = 0.0f;
        #pragma unroll
        for (int g = 0; g < 8; g++) v += part[t + 128 * g];
        pooled[t] = v;
    }
    __syncthreads();

    // layer1: 256 outputs, 4-way K split (K=128)
    {
        int o = t & 255, ch = t >> 8;
        float v = 0.0f;
        int k0 = ch * 32;
        #pragma unroll
        for (int k = 0; k < 32; k++)
            v = fmaf(pooled[k0 + k], W3[(k0 + k) * R1 + o], v);
        __syncthreads();
        part[t] = v;
    }
    __syncthreads();
    if (t < R1)
        r1[t] = fmaxf(b3[t] + part[t] + part[t + 256] + part[t + 512] + part[t + 768], 0.0f);
    __syncthreads();

    // layer2: 128 outputs, 8-way K split (K=256)
    {
        int o = t & 127, ch = t >> 7;
        float v = 0.0f;
        int k0 = ch * 32;
        #pragma unroll
        for (int k = 0; k < 32; k++)
            v = fmaf(r1[k0 + k], W4[(k0 + k) * R2 + o], v);
        __syncthreads();
        part[t] = v;
    }
    __syncthreads();
    if (t < R2) {
        float v = b4[t];
        #pragma unroll
        for (int j = 0; j < 8; j++) v += part[t + 128 * j];
        r2[t] = fmaxf(v, 0.0f);
    }
    __syncthreads();

    // layer3: 64 outputs, 16-way K split (K=128)
    {
        int o = t & 63, ch = t >> 6;
        float v = 0.0f;
        int k0 = ch * 8;
        #pragma unroll
        for (int k = 0; k < 8; k++)
            v = fmaf(r2[k0 + k], W5[(k0 + k) * OD + o], v);
        __syncthreads();
        part[t] = v;
    }
    __syncthreads();
    if (t < OD) {
        float v = b5[t];
        #pragma unroll
        for (int j = 0; j < 16; j++) v += part[t + 64 * j];
        out[b * OD + t] = v;
    }
}

// ---------------------------------------------------------------------------
extern "C" void kernel_launch(void* const* d_in, const int* in_sizes, int n_in,
                              void* d_out, int out_size) {
    const float* dm      = (const float*)d_in[0];
    const int*   lengths = (const int*)  d_in[1];
    const float* W1 = (const float*)d_in[2],  *b1 = (const float*)d_in[3];
    const float* W2 = (const float*)d_in[4],  *b2 = (const float*)d_in[5];
    const float* W3 = (const float*)d_in[6],  *b3 = (const float*)d_in[7];
    const float* W4 = (const float*)d_in[8],  *b4 = (const float*)d_in[9];
    const float* W5 = (const float*)d_in[10], *b5 = (const float*)d_in[11];
    float* out = (float*)d_out;

    const int smem_eval = NSEG * 130 * 8 + NSEG * 130 * 4
                        + (1024 + P2 + R1 + R2) * 4;
    cudaFuncSetAttribute((const void*)evalhead_kernel,
                         cudaFuncAttributeMaxDynamicSharedMemorySize, smem_eval);

    setup0<<<297, 256>>>(W1, b1);
    setup_tables<<<NSEG, P2>>>(W1, b1, W2, b2);
    hist_kernel<<<HIST_GRID, 256>>>(dm, lengths);
    evalhead_kernel<<<NB, 1024, smem_eval>>>(W3, b3, W4, b4, W5, b5, out);
}

// round 4
// speedup vs baseline: 1.7882x; 1.1278x over previous
#include <cuda_runtime.h>
#include <math_constants.h>

// ScalarDistanceDeepSet via exact piecewise-linear collapse + cell histogram.
// g(s) (1->64->128 relu MLP) is piecewise-linear: 64 layer-1 breakpoints -> 65
// segments with per-(segment,feature) (a,c); per-feature relu crossings theta
// (clamped into their segment) give 8384 global sorted boundaries -> 8385 cells
// on which every feature is linear. Per pair: one branchless 14-step search
// (ILP-4 across rows) + 2 integer atomics (deterministic). Pooled recovered by
// per-segment warp scans + range algebra (one warp per (batch,segment)), then
// a small fused head MLP.

#define NB    32
#define NN    256
#define P1    64
#define P2    128
#define R1    256
#define R2    128
#define OD    64
#define NSEG  65
#define NCELL 129
#define NSLOT (NSEG * NCELL)      // 8385 cells
#define NBND  (NSLOT - 1)         // 8384 boundaries
#define SCALE_F   67108864.0f     // 2^26
#define INV_SCALE (1.0 / 67108864.0)
#define HIST_GRID 592
#define NGRP  9                   // ceil(65/8) segment groups

__device__ float     g_tsorted[P1];
__device__ int       g_rank[P1];
__device__ float     g_A[NSEG * P2];
__device__ float     g_C[NSEG * P2];
__device__ float     g_bnd[NBND];                 // flat sorted boundaries
__device__ int2      g_range[NSEG * P2];          // [rlo, rhi) active cell range
__device__ long long g_hs[NB * NSLOT];            // fixed-point sum(s) per cell
__device__ int       g_hc[NB * NSLOT];            // count per cell
__device__ float     g_ppart[NB * NGRP * P2];     // pooled partials

// ---------------------------------------------------------------------------
// Setup 0: block 0 computes breakpoints + ranks; other blocks zero histograms.
// ---------------------------------------------------------------------------
__global__ void setup0(const float* __restrict__ W1,
                       const float* __restrict__ b1) {
    if (blockIdx.x == 0) {
        __shared__ float t[P1];
        int k = threadIdx.x;
        float tk = 0.0f;
        if (k < P1) {
            float w = W1[k], b = b1[k];
            tk = (w != 0.0f) ? (-b / w) : CUDART_INF_F;
            t[k] = tk;
        }
        __syncthreads();
        if (k < P1) {
            int r = 0;
            for (int kk = 0; kk < P1; kk++) {
                float tv = t[kk];
                if (tv < tk || (tv == tk && kk < k)) r++;
            }
            g_rank[k] = r;
            g_tsorted[r] = tk;
        }
    } else {
        int idx = (blockIdx.x - 1) * blockDim.x + threadIdx.x;
        int stride = (gridDim.x - 1) * blockDim.x;
        for (int i = idx; i < NB * NSLOT; i += stride) {
            g_hs[i] = 0;
            g_hc[i] = 0;
        }
    }
}

// ---------------------------------------------------------------------------
// Setup 1: per-(segment m, feature f) exact (a,c), clamped relu crossing theta,
// its rank p within the segment, active cell range, and the flat boundary
// array: g_bnd[m*129 + p] = theta, g_bnd[m*129 + 128] = t_sorted[m].
// ---------------------------------------------------------------------------
__global__ void setup_tables(const float* __restrict__ W1,
                             const float* __restrict__ b1,
                             const float* __restrict__ W2,
                             const float* __restrict__ b2) {
    __shared__ float sth[P2];
    int m = blockIdx.x;
    int f = threadIdx.x;
    float a = 0.0f, c = b2[f];
    for (int k = 0; k < P1; k++) {
        float w = W1[k], b = b1[k];
        int r = g_rank[k];
        bool active = (w > 0.0f) ? (m > r)
                    : (w < 0.0f) ? (m <= r)
                    : (b > 0.0f);
        if (active) {
            float w2 = W2[k * P2 + f];
            a = fmaf(w, w2, a);
            c = fmaf(b, w2, c);
        }
    }
    int idx = m * P2 + f;
    g_A[idx] = a;
    g_C[idx] = c;

    float lo_t = (m == 0)        ? -CUDART_INF_F : g_tsorted[m - 1];
    float hi_t = (m == NSEG - 1) ?  CUDART_INF_F : g_tsorted[m];
    float th;
    if (a != 0.0f) {
        th = -c / a;
        th = fminf(fmaxf(th, lo_t), hi_t);
    } else {
        th = lo_t;
    }
    sth[f] = th;
    __syncthreads();
    int p = 0;
    for (int k = 0; k < P2; k++) {
        float tv = sth[k];
        if (tv < th || (tv == th && k < f)) p++;
    }
    g_bnd[m * NCELL + p] = th;
    if (f == 0 && m < NSEG - 1) g_bnd[m * NCELL + P2] = g_tsorted[m];

    int rlo, rhi;
    if (a > 0.0f)      { rlo = p + 1; rhi = NCELL; }
    else if (a < 0.0f) { rlo = 0;     rhi = p + 1; }
    else               { rlo = 0;     rhi = (c > 0.0f) ? NCELL : 0; }
    g_range[idx] = make_int2(rlo, rhi);
}

// ---------------------------------------------------------------------------
// Histogram. 1-D grid; task = 4 consecutive rows of one batch. Thread tid owns
// column j=tid across the 4 rows -> 4 independent branchless searches per
// thread (ILP-4 hides the dependent-LDS chain). 2 atomics per valid pair.
// ---------------------------------------------------------------------------
__global__ void __launch_bounds__(256)
hist_kernel(const float* __restrict__ dm, const int* __restrict__ lengths) {
    __shared__ float sb[NBND];     // 33.5 KB
    int tid = threadIdx.x;
    for (int i = tid; i < NBND; i += 256) sb[i] = g_bnd[i];
    __syncthreads();

    const int ntask = NB * (NN / 4);   // 2048
    for (int task = blockIdx.x; task < ntask; task += gridDim.x) {
        int b  = task & 31;
        int i0 = (task >> 5) << 2;
        int L  = __ldg(lengths + b);
        if (i0 >= L - 1) continue;

        const float* rowp = dm + ((size_t)b << 16) + ((size_t)i0 << 8) + tid;
        float s[4]; int n[4], pos[4];
        #pragma unroll
        for (int r = 0; r < 4; r++) {
            int i = i0 + r;
            bool valid = (i < L - 1) && (tid > i) && (tid < L);
            s[r]   = valid ? rowp[r << 8] : 0.0f;
            pos[r] = 0;
            n[r]   = valid ? NBND : 0;
        }
        #pragma unroll
        for (int it = 0; it < 14; it++) {
            #pragma unroll
            for (int r = 0; r < 4; r++) {
                if (n[r] > 0) {
                    int half = n[r] >> 1;
                    int mid  = pos[r] + half;
                    if (sb[mid] < s[r]) { pos[r] = mid + 1; n[r] -= half + 1; }
                    else                { n[r] = half; }
                }
            }
        }
        unsigned long long* hsb = (unsigned long long*)g_hs + (size_t)b * NSLOT;
        int* hcb = g_hc + (size_t)b * NSLOT;
        #pragma unroll
        for (int r = 0; r < 4; r++) {
            int i = i0 + r;
            bool valid = (i < L - 1) && (tid > i) && (tid < L);
            if (valid) {
                long long q = llrintf(s[r] * SCALE_F);
                atomicAdd(&hsb[pos[r]], (unsigned long long)q);
                atomicAdd(&hcb[pos[r]], 1);
            }
        }
    }
}

// ---------------------------------------------------------------------------
// Pooled partials: grid (NGRP, NB), 256 threads = 8 warps. Warp w handles
// segment m = g*8 + w: 129-cell scan via warp shuffles, then its contribution
// to all 128 pooled features. Block reduces 8 warps -> g_ppart[b][g][f].
// ---------------------------------------------------------------------------
__global__ void __launch_bounds__(256)
pooled_kernel() {
    __shared__ long long ps[8][130];
    __shared__ int       pc[8][130];
    __shared__ float     part[8][P2];

    int t = threadIdx.x, warp = t >> 5, lane = t & 31;
    int g = blockIdx.x, b = blockIdx.y;
    int m = g * 8 + warp;

    float facc[4] = {0.0f, 0.0f, 0.0f, 0.0f};
    if (m < NSEG) {
        const long long* hs = g_hs + (size_t)b * NSLOT + m * NCELL;
        const int*       hc = g_hc + (size_t)b * NSLOT + m * NCELL;
        int base = lane * 4;
        int ncl  = (lane == 31) ? 5 : 4;
        long long ls[5]; int lc[5];
        long long runS = 0; int runC = 0;
        #pragma unroll
        for (int e = 0; e < 5; e++) {
            if (e < ncl) {
                ls[e] = runS; lc[e] = runC;
                runS += hs[base + e];
                runC += hc[base + e];
            }
        }
        long long incS = runS; int incC = runC;
        #pragma unroll
        for (int off = 1; off < 32; off <<= 1) {
            long long vS = __shfl_up_sync(0xffffffffu, incS, off);
            int       vC = __shfl_up_sync(0xffffffffu, incC, off);
            if (lane >= off) { incS += vS; incC += vC; }
        }
        long long exS = incS - runS; int exC = incC - runC;
        #pragma unroll
        for (int e = 0; e < 5; e++) {
            if (e < ncl) {
                ps[warp][base + e] = exS + ls[e];
                pc[warp][base + e] = exC + lc[e];
            }
        }
        if (lane == 31) { ps[warp][NCELL] = incS; pc[warp][NCELL] = incC; }
        __syncwarp();

        #pragma unroll
        for (int ff = 0; ff < 4; ff++) {
            int f = lane + 32 * ff;
            int idx = m * P2 + f;
            float a = g_A[idx], c = g_C[idx];
            int2 rg = g_range[idx];
            long long ds = ps[warp][rg.y] - ps[warp][rg.x];
            int       dc = pc[warp][rg.y] - pc[warp][rg.x];
            facc[ff] = a * (float)((double)ds * INV_SCALE) + c * (float)dc;
        }
    }
    #pragma unroll
    for (int ff = 0; ff < 4; ff++)
        part[warp][lane + 32 * ff] = facc[ff];
    __syncthreads();

    if (t < P2) {
        float v = 0.0f;
        #pragma unroll
        for (int w = 0; w < 8; w++) v += part[w][t];
        g_ppart[((size_t)b * NGRP + g) * P2 + t] = v;
    }
}

// ---------------------------------------------------------------------------
// Head: grid NB, 512 threads. Reduce NGRP partials -> pooled, then the
// 128->256->128->64 MLP with K-splits.
// ---------------------------------------------------------------------------
__global__ void __launch_bounds__(512)
head_kernel(const float* __restrict__ W3, const float* __restrict__ b3,
            const float* __restrict__ W4, const float* __restrict__ b4,
            const float* __restrict__ W5, const float* __restrict__ b5,
            float* __restrict__ out) {
    __shared__ float pooled[P2];
    __shared__ float r1v[R1];
    __shared__ float r2v[R2];
    __shared__ float part[512];
    int b = blockIdx.x, t = threadIdx.x;

    if (t < P2) {
        float v = 0.0f;
        #pragma unroll
        for (int g = 0; g < NGRP; g++)
            v += g_ppart[((size_t)b * NGRP + g) * P2 + t];
        pooled[t] = v;
    }
    __syncthreads();

    {   // layer1: 256 outputs, 2-way K split (K=128)
        int o = t & 255, h = t >> 8;
        float v = 0.0f;
        int k0 = h * 64;
        #pragma unroll
        for (int k = 0; k < 64; k++)
            v = fmaf(pooled[k0 + k], W3[(k0 + k) * R1 + o], v);
        part[t] = v;
    }
    __syncthreads();
    if (t < R1)
        r1v[t] = fmaxf(b3[t] + part[t] + part[t + 256], 0.0f);
    __syncthreads();

    {   // layer2: 128 outputs, 4-way K split (K=256)
        int o = t & 127, ch = t >> 7;
        float v = 0.0f;
        int k0 = ch * 64;
        #pragma unroll
        for (int k = 0; k < 64; k++)
            v = fmaf(r1v[k0 + k], W4[(k0 + k) * R2 + o], v);
        __syncthreads();
        part[t] = v;
    }
    __syncthreads();
    if (t < R2) {
        float v = b4[t];
        #pragma unroll
        for (int j = 0; j < 4; j++) v += part[t + 128 * j];
        r2v[t] = fmaxf(v, 0.0f);
    }
    __syncthreads();

    {   // layer3: 64 outputs, 8-way K split (K=128)
        int o = t & 63, ch = t >> 6;
        float v = 0.0f;
        int k0 = ch * 16;
        #pragma unroll
        for (int k = 0; k < 16; k++)
            v = fmaf(r2v[k0 + k], W5[(k0 + k) * OD + o], v);
        __syncthreads();
        part[t] = v;
    }
    __syncthreads();
    if (t < OD) {
        float v = b5[t];
        #pragma unroll
        for (int j = 0; j < 8; j++) v += part[t + 64 * j];
        out[b * OD + t] = v;
    }
}

// ---------------------------------------------------------------------------
extern "C" void kernel_launch(void* const* d_in, const int* in_sizes, int n_in,
                              void* d_out, int out_size) {
    const float* dm      = (const float*)d_in[0];
    const int*   lengths = (const int*)  d_in[1];
    const float* W1 = (const float*)d_in[2],  *b1 = (const float*)d_in[3];
    const float* W2 = (const float*)d_in[4],  *b2 = (const float*)d_in[5];
    const float* W3 = (const float*)d_in[6],  *b3 = (const float*)d_in[7];
    const float* W4 = (const float*)d_in[8],  *b4 = (const float*)d_in[9];
    const float* W5 = (const float*)d_in[10], *b5 = (const float*)d_in[11];
    float* out = (float*)d_out;

    setup0<<<297, 256>>>(W1, b1);
    setup_tables<<<NSEG, P2>>>(W1, b1, W2, b2);
    hist_kernel<<<HIST_GRID, 256>>>(dm, lengths);
    pooled_kernel<<<dim3(NGRP, NB), 256>>>();
    head_kernel<<<NB, 512>>>(W3, b3, W4, b4, W5, b5, out);
}